// round 3
// baseline (speedup 1.0000x reference)
#include <cuda_runtime.h>
#include <cmath>
#include <cstring>
#include <vector>
#include <complex>
#include <algorithm>
#include <numeric>

#define NAO      14
#define NAO2     196
#define SPB      64          // samples per block
#define XSTRIDE  65          // odd stride -> conflict-free both phases
#define MAXT     2120        // >= worst-case 2116 terms
#define SMEM_BYTES (2 * NAO2 * XSTRIDE * 4)

// ---------------------------------------------------------------------------
// Sparse matrix of the full linear map, passed as a (large) kernel parameter.
// term[t].x = coefficient, term[t].y = (input column * XSTRIDE) as int bits.
// ---------------------------------------------------------------------------
struct Params {
    float2         term[MAXT];
    unsigned short roff[NAO2 + 4];
};

__global__ void __launch_bounds__(256, 2)
te_kernel(const float* __restrict__ x, float* __restrict__ out, int nsamp,
          const __grid_constant__ Params P)
{
    extern __shared__ float sm[];
    float* xs = sm;                     // [196][65]  element-major, sample fastest
    float* os = sm + NAO2 * XSTRIDE;    // [196][65]  output rows

    const int n0    = blockIdx.x * SPB;
    int valid       = nsamp - n0; if (valid > SPB) valid = SPB;
    const int total = valid * NAO2;

    // ---- stage x (coalesced global reads, ~conflict-free smem writes) ----
    const float* src = x + (long long)n0 * NAO2;
    for (int f = threadIdx.x; f < total; f += 256) {
        unsigned s = (unsigned)f / (unsigned)NAO2;
        unsigned e = (unsigned)f - s * (unsigned)NAO2;
        xs[e * XSTRIDE + s] = src[f];
    }
    __syncthreads();

    // ---- sparse matvec: warp w owns output rows w, w+8, ... ; lane = sample
    const int wid  = threadIdx.x >> 5;
    const int lane = threadIdx.x & 31;
    for (int k = wid; k < NAO2; k += 8) {
        const int t0 = P.roff[k];
        const int t1 = P.roff[k + 1];
        float a0 = 0.f, a1 = 0.f;
        for (int t = t0; t < t1; ++t) {
            const float2 tv = P.term[t];
            const int c65 = __float_as_int(tv.y);
            a0 = fmaf(tv.x, xs[c65 + lane],      a0);
            a1 = fmaf(tv.x, xs[c65 + 32 + lane], a1);
        }
        os[k * XSTRIDE + lane]      = a0;
        os[k * XSTRIDE + 32 + lane] = a1;
    }
    __syncthreads();

    // ---- write out (coalesced global writes) ----
    float* dst = out + (long long)n0 * NAO2;
    for (int f = threadIdx.x; f < total; f += 256) {
        unsigned s = (unsigned)f / (unsigned)NAO2;
        unsigned e = (unsigned)f - s * (unsigned)NAO2;
        dst[f] = os[e * XSTRIDE + s];
    }
}

// ===========================================================================
// Host-side construction of the CG / Wigner-3j sparse matrix (double prec).
// Runs only during the correctness call and graph capture — never timed.
// ===========================================================================
namespace cgbuild {

static double fct(int n) { double r = 1.0; for (int i = 2; i <= n; ++i) r *= i; return r; }

static double su2cg(int j1, int m1, int j2, int m2, int j3, int m3)
{
    if (m3 != m1 + m2) return 0.0;
    int vmin = std::max(std::max(-j1 + j2 + m3, -j1 + m1), 0);
    int vmax = std::min(std::min(j2 + j3 + m1, j3 - j1 + j2), j3 + m3);
    double c = std::sqrt((2.0 * j3 + 1) * fct(j3 + j1 - j2) * fct(j3 - j1 + j2) *
                         fct(j1 + j2 - j3) * fct(j3 + m3) * fct(j3 - m3) /
                         (fct(j1 + j2 + j3 + 1) * fct(j1 - m1) * fct(j1 + m1) *
                          fct(j2 - m2) * fct(j2 + m2)));
    double s = 0.0;
    for (int v = vmin; v <= vmax; ++v) {
        double sign = ((v + j2 + m2) & 1) ? -1.0 : 1.0;
        s += sign * fct(j2 + j3 + m1 - v) * fct(j1 - m1 + v) /
             (fct(v) * fct(j3 - j1 + j2 - v) * fct(j3 + m3 - v) * fct(v + j1 - j2 - m3));
    }
    return c * s;
}

typedef std::complex<double> C;

static std::vector<C> qmat(int l)
{
    int n = 2 * l + 1;
    std::vector<C> q((size_t)n * n, C(0, 0));
    const double is2 = 1.0 / std::sqrt(2.0);
    for (int m = -l; m < 0; ++m) {
        q[(size_t)(l + m) * n + (l - m)] = C(is2, 0);    // col l+|m|
        q[(size_t)(l + m) * n + (l + m)] = C(0, -is2);   // col l-|m|
    }
    q[(size_t)l * n + l] = C(1, 0);
    for (int m = 1; m <= l; ++m) {
        double sg = (m & 1) ? -1.0 : 1.0;
        q[(size_t)(l + m) * n + (l + m)] = C(sg * is2, 0);
        q[(size_t)(l + m) * n + (l - m)] = C(0, sg * is2);
    }
    C f(1, 0), mi(0, -1);
    for (int t = 0; t < l; ++t) f *= mi;                  // (-1j)^l
    for (auto& z : q) z *= f;
    return q;
}

static void wigner3j(int l1, int l2, int l3, double* outv)
{
    int n1 = 2 * l1 + 1, n2 = 2 * l2 + 1, n3 = 2 * l3 + 1;
    std::vector<double> csu2((size_t)n1 * n2 * n3, 0.0);
    for (int m1 = -l1; m1 <= l1; ++m1)
        for (int m2 = -l2; m2 <= l2; ++m2) {
            int m3 = m1 + m2;
            if (m3 >= -l3 && m3 <= l3)
                csu2[((size_t)(l1 + m1) * n2 + (l2 + m2)) * n3 + (l3 + m3)] =
                    su2cg(l1, m1, l2, m2, l3, m3);
        }
    std::vector<C> q1 = qmat(l1), q2 = qmat(l2), q3 = qmat(l3);
    std::vector<C> cc((size_t)n1 * n2 * n3, C(0, 0));
    // cc[a][b][c] = sum_{i,k,n} q1[i][a] q2[k][b] conj(q3[n][c]) csu2[i][k][n]
    for (int i = 0; i < n1; ++i)
        for (int k = 0; k < n2; ++k)
            for (int n = 0; n < n3; ++n) {
                double s = csu2[((size_t)i * n2 + k) * n3 + n];
                if (s == 0.0) continue;
                for (int a = 0; a < n1; ++a) {
                    C qa = q1[(size_t)i * n1 + a];
                    if (qa.real() == 0.0 && qa.imag() == 0.0) continue;
                    for (int b = 0; b < n2; ++b) {
                        C qab = qa * q2[(size_t)k * n2 + b] * s;
                        for (int c = 0; c < n3; ++c)
                            cc[((size_t)a * n2 + b) * n3 + c] += qab * std::conj(q3[(size_t)n * n3 + c]);
                    }
                }
            }
    double nre = 0, nim = 0;
    for (auto& z : cc) { nre += z.real() * z.real(); nim += z.imag() * z.imag(); }
    bool useRe = std::sqrt(nre) >= std::sqrt(nim);
    double nn  = std::sqrt(useRe ? nre : nim);
    for (size_t t = 0; t < cc.size(); ++t)
        outv[t] = (useRe ? cc[t].real() : cc[t].imag()) / nn;
}

static void build_params(Params& P)
{
    memset(&P, 0, sizeof(P));
    const int LSh[6]    = {0, 0, 0, 1, 1, 2};
    const int IDXC[NAO] = {0, 1, 2, 5, 3, 4, 8, 6, 7, 11, 13, 9, 12, 10};
    int inv[NAO];
    for (int i = 0; i < NAO; ++i) inv[IDXC[i]] = i;

    struct Blk { int rs, nr, cs, nc, L, par; std::vector<double> cg; };
    std::vector<Blk> blks;
    int rs = 0;
    for (int a = 0; a < 6; ++a) {
        int li = LSh[a], nr = 2 * li + 1, cs = 0;
        for (int b = 0; b < 6; ++b) {
            int lj = LSh[b], nc = 2 * lj + 1;
            for (int L = std::abs(li - lj); L <= li + lj; ++L) {
                Blk bl; bl.rs = rs; bl.nr = nr; bl.cs = cs; bl.nc = nc; bl.L = L;
                bl.par = ((li + lj) & 1) ? -1 : 1;
                bl.cg.resize((size_t)(2 * L + 1) * nr * nc);
                wigner3j(L, li, lj, bl.cg.data());
                blks.push_back(std::move(bl));
            }
            cs += nc;
        }
        rs += nr;
    }

    // stable sort by (L, parity) — matches Python's stable `sorted`
    std::vector<int> perm(blks.size());
    std::iota(perm.begin(), perm.end(), 0);
    std::stable_sort(perm.begin(), perm.end(), [&](int i, int j) {
        if (blks[i].L != blks[j].L) return blks[i].L < blks[j].L;
        return blks[i].par < blks[j].par;
    });
    std::vector<int> outbase(blks.size());
    int base = 0;
    for (int idx : perm) { outbase[idx] = base; base += 2 * blks[idx].L + 1; }

    std::vector<std::vector<std::pair<int, float>>> rows(NAO2);
    for (size_t bi = 0; bi < blks.size(); ++bi) {
        Blk& bl = blks[bi];
        int w = 2 * bl.L + 1;
        for (int k = 0; k < w; ++k) {
            int r = outbase[bi] + k;
            for (int i = 0; i < bl.nr; ++i)
                for (int j = 0; j < bl.nc; ++j) {
                    double v = bl.cg[((size_t)k * bl.nr + i) * bl.nc + j];
                    if (std::fabs(v) > 1e-9) {
                        int col = inv[bl.rs + i] * NAO + inv[bl.cs + j];
                        rows[r].push_back({col * XSTRIDE, (float)v});
                    }
                }
        }
    }

    int t = 0;
    for (int r = 0; r < NAO2; ++r) {
        P.roff[r] = (unsigned short)t;
        for (auto& pr : rows[r]) {
            if (t >= MAXT) break;
            P.term[t].x = pr.second;
            int c = pr.first;
            memcpy(&P.term[t].y, &c, 4);
            ++t;
        }
    }
    P.roff[NAO2] = (unsigned short)t;
}

} // namespace cgbuild

extern "C" void kernel_launch(void* const* d_in, const int* in_sizes, int n_in,
                              void* d_out, int out_size)
{
    (void)n_in; (void)out_size;
    const float* x  = (const float*)d_in[0];
    float*      out = (float*)d_out;
    const int nsamp = in_sizes[0] / NAO2;

    Params P;
    cgbuild::build_params(P);

    cudaFuncSetAttribute(te_kernel, cudaFuncAttributeMaxDynamicSharedMemorySize, SMEM_BYTES);

    const int grid = (nsamp + SPB - 1) / SPB;
    te_kernel<<<grid, 256, SMEM_BYTES>>>(x, out, nsamp, P);
}

// round 5
// speedup vs baseline: 1.1559x; 1.1559x over previous
#include <cuda_runtime.h>
#include <cmath>
#include <cstring>
#include <vector>
#include <complex>
#include <algorithm>
#include <numeric>

#define NAO      14
#define NAO2     196
#define SPB      64          // samples per block
#define XSTRIDE  65          // odd stride -> conflict-free both phases
#define NTHR     512
#define NWARP    16
#define MAXT     2120        // >= worst-case 2116 terms
#define SMEM_BYTES (2 * NAO2 * XSTRIDE * 4)

// ---------------------------------------------------------------------------
// Sparse matrix of the full linear map, passed as a (large) kernel parameter.
// term[t].x = coefficient, term[t].y = (input column * XSTRIDE) as int bits.
// ---------------------------------------------------------------------------
struct Params {
    float2         term[MAXT];
    unsigned short roff[NAO2 + 4];
};

__global__ void __launch_bounds__(NTHR, 2)
te_kernel(const float* __restrict__ x, float* __restrict__ out, int nsamp,
          const __grid_constant__ Params P)
{
    extern __shared__ float sm[];
    float* xs = sm;                     // [196][65]  element-major, sample fastest
    float* os = sm + NAO2 * XSTRIDE;    // [196][65]  output rows

    const int n0    = blockIdx.x * SPB;
    int valid       = nsamp - n0; if (valid > SPB) valid = SPB;
    const int total = valid * NAO2;
    const int tid   = threadIdx.x;

    // (e,s) for f = tid, then incremental update for f += 512 (= 2*196 + 120)
    int e0 = tid, s0 = 0;
    if (e0 >= NAO2)     { e0 -= NAO2; s0 = 1; }
    if (e0 >= NAO2)     { e0 -= NAO2; s0 = 2; }   // tid < 512 < 3*196

    // ---- stage x (coalesced global reads, conflict-free smem writes) ----
    {
        const float* src = x + (long long)n0 * NAO2;
        int e = e0, s = s0;
        #pragma unroll 4
        for (int f = tid; f < total; f += NTHR) {
            xs[e * XSTRIDE + s] = src[f];
            e += 120; s += 2;
            if (e >= NAO2) { e -= NAO2; s += 1; }
        }
    }
    __syncthreads();

    // ---- sparse matvec: warp w owns output rows w, w+16, ... ; lane = sample
    const int wid  = tid >> 5;
    const int lane = tid & 31;
    for (int k = wid; k < NAO2; k += NWARP) {
        const int t0 = P.roff[k];
        const int t1 = P.roff[k + 1];
        float a0 = 0.f, a1 = 0.f;
        for (int t = t0; t < t1; ++t) {
            const float2 tv = P.term[t];
            const int c65 = __float_as_int(tv.y);
            a0 = fmaf(tv.x, xs[c65 + lane],      a0);
            a1 = fmaf(tv.x, xs[c65 + 32 + lane], a1);
        }
        os[k * XSTRIDE + lane]      = a0;
        os[k * XSTRIDE + 32 + lane] = a1;
    }
    __syncthreads();

    // ---- write out (coalesced global writes) ----
    {
        float* dst = out + (long long)n0 * NAO2;
        int e = e0, s = s0;
        #pragma unroll 4
        for (int f = tid; f < total; f += NTHR) {
            dst[f] = os[e * XSTRIDE + s];
            e += 120; s += 2;
            if (e >= NAO2) { e -= NAO2; s += 1; }
        }
    }
}

// ===========================================================================
// Host-side construction of the CG / Wigner-3j sparse matrix (double prec).
// Runs only during the correctness call and graph capture — never timed.
// ===========================================================================
namespace cgbuild {

static double fct(int n) { double r = 1.0; for (int i = 2; i <= n; ++i) r *= i; return r; }

static double su2cg(int j1, int m1, int j2, int m2, int j3, int m3)
{
    if (m3 != m1 + m2) return 0.0;
    int vmin = std::max(std::max(-j1 + j2 + m3, -j1 + m1), 0);
    int vmax = std::min(std::min(j2 + j3 + m1, j3 - j1 + j2), j3 + m3);
    double c = std::sqrt((2.0 * j3 + 1) * fct(j3 + j1 - j2) * fct(j3 - j1 + j2) *
                         fct(j1 + j2 - j3) * fct(j3 + m3) * fct(j3 - m3) /
                         (fct(j1 + j2 + j3 + 1) * fct(j1 - m1) * fct(j1 + m1) *
                          fct(j2 - m2) * fct(j2 + m2)));
    double s = 0.0;
    for (int v = vmin; v <= vmax; ++v) {
        double sign = ((v + j2 + m2) & 1) ? -1.0 : 1.0;
        s += sign * fct(j2 + j3 + m1 - v) * fct(j1 - m1 + v) /
             (fct(v) * fct(j3 - j1 + j2 - v) * fct(j3 + m3 - v) * fct(v + j1 - j2 - m3));
    }
    return c * s;
}

typedef std::complex<double> C;

static std::vector<C> qmat(int l)
{
    int n = 2 * l + 1;
    std::vector<C> q((size_t)n * n, C(0, 0));
    const double is2 = 1.0 / std::sqrt(2.0);
    for (int m = -l; m < 0; ++m) {
        q[(size_t)(l + m) * n + (l - m)] = C(is2, 0);    // col l+|m|
        q[(size_t)(l + m) * n + (l + m)] = C(0, -is2);   // col l-|m|
    }
    q[(size_t)l * n + l] = C(1, 0);
    for (int m = 1; m <= l; ++m) {
        double sg = (m & 1) ? -1.0 : 1.0;
        q[(size_t)(l + m) * n + (l + m)] = C(sg * is2, 0);
        q[(size_t)(l + m) * n + (l - m)] = C(0, sg * is2);
    }
    C f(1, 0), mi(0, -1);
    for (int t = 0; t < l; ++t) f *= mi;                  // (-1j)^l
    for (auto& z : q) z *= f;
    return q;
}

static void wigner3j(int l1, int l2, int l3, double* outv)
{
    int n1 = 2 * l1 + 1, n2 = 2 * l2 + 1, n3 = 2 * l3 + 1;
    std::vector<double> csu2((size_t)n1 * n2 * n3, 0.0);
    for (int m1 = -l1; m1 <= l1; ++m1)
        for (int m2 = -l2; m2 <= l2; ++m2) {
            int m3 = m1 + m2;
            if (m3 >= -l3 && m3 <= l3)
                csu2[((size_t)(l1 + m1) * n2 + (l2 + m2)) * n3 + (l3 + m3)] =
                    su2cg(l1, m1, l2, m2, l3, m3);
        }
    std::vector<C> q1 = qmat(l1), q2 = qmat(l2), q3 = qmat(l3);
    std::vector<C> cc((size_t)n1 * n2 * n3, C(0, 0));
    // cc[a][b][c] = sum_{i,k,n} q1[i][a] q2[k][b] conj(q3[n][c]) csu2[i][k][n]
    for (int i = 0; i < n1; ++i)
        for (int k = 0; k < n2; ++k)
            for (int n = 0; n < n3; ++n) {
                double s = csu2[((size_t)i * n2 + k) * n3 + n];
                if (s == 0.0) continue;
                for (int a = 0; a < n1; ++a) {
                    C qa = q1[(size_t)i * n1 + a];
                    if (qa.real() == 0.0 && qa.imag() == 0.0) continue;
                    for (int b = 0; b < n2; ++b) {
                        C qab = qa * q2[(size_t)k * n2 + b] * s;
                        for (int c = 0; c < n3; ++c)
                            cc[((size_t)a * n2 + b) * n3 + c] += qab * std::conj(q3[(size_t)n * n3 + c]);
                    }
                }
            }
    double nre = 0, nim = 0;
    for (auto& z : cc) { nre += z.real() * z.real(); nim += z.imag() * z.imag(); }
    bool useRe = std::sqrt(nre) >= std::sqrt(nim);
    double nn  = std::sqrt(useRe ? nre : nim);
    for (size_t t = 0; t < cc.size(); ++t)
        outv[t] = (useRe ? cc[t].real() : cc[t].imag()) / nn;
}

static void build_params(Params& P)
{
    memset(&P, 0, sizeof(P));
    const int LSh[6]    = {0, 0, 0, 1, 1, 2};
    const int IDXC[NAO] = {0, 1, 2, 5, 3, 4, 8, 6, 7, 11, 13, 9, 12, 10};
    int inv[NAO];
    for (int i = 0; i < NAO; ++i) inv[IDXC[i]] = i;

    struct Blk { int rs, nr, cs, nc, L, par; std::vector<double> cg; };
    std::vector<Blk> blks;
    int rs = 0;
    for (int a = 0; a < 6; ++a) {
        int li = LSh[a], nr = 2 * li + 1, cs = 0;
        for (int b = 0; b < 6; ++b) {
            int lj = LSh[b], nc = 2 * lj + 1;
            for (int L = std::abs(li - lj); L <= li + lj; ++L) {
                Blk bl; bl.rs = rs; bl.nr = nr; bl.cs = cs; bl.nc = nc; bl.L = L;
                bl.par = ((li + lj) & 1) ? -1 : 1;
                bl.cg.resize((size_t)(2 * L + 1) * nr * nc);
                wigner3j(L, li, lj, bl.cg.data());
                blks.push_back(std::move(bl));
            }
            cs += nc;
        }
        rs += nr;
    }

    // stable sort by (L, parity) — matches Python's stable `sorted`
    std::vector<int> perm(blks.size());
    std::iota(perm.begin(), perm.end(), 0);
    std::stable_sort(perm.begin(), perm.end(), [&](int i, int j) {
        if (blks[i].L != blks[j].L) return blks[i].L < blks[j].L;
        return blks[i].par < blks[j].par;
    });
    std::vector<int> outbase(blks.size());
    int base = 0;
    for (int idx : perm) { outbase[idx] = base; base += 2 * blks[idx].L + 1; }

    std::vector<std::vector<std::pair<int, float>>> rows(NAO2);
    for (size_t bi = 0; bi < blks.size(); ++bi) {
        Blk& bl = blks[bi];
        int w = 2 * bl.L + 1;
        for (int k = 0; k < w; ++k) {
            int r = outbase[bi] + k;
            for (int i = 0; i < bl.nr; ++i)
                for (int j = 0; j < bl.nc; ++j) {
                    double v = bl.cg[((size_t)k * bl.nr + i) * bl.nc + j];
                    if (std::fabs(v) > 1e-9) {
                        int col = inv[bl.rs + i] * NAO + inv[bl.cs + j];
                        rows[r].push_back({col * XSTRIDE, (float)v});
                    }
                }
        }
    }

    int t = 0;
    for (int r = 0; r < NAO2; ++r) {
        P.roff[r] = (unsigned short)t;
        for (auto& pr : rows[r]) {
            if (t >= MAXT) break;
            P.term[t].x = pr.second;
            int c = pr.first;
            memcpy(&P.term[t].y, &c, 4);
            ++t;
        }
    }
    P.roff[NAO2] = (unsigned short)t;
}

} // namespace cgbuild

extern "C" void kernel_launch(void* const* d_in, const int* in_sizes, int n_in,
                              void* d_out, int out_size)
{
    (void)n_in; (void)out_size;
    const float* x  = (const float*)d_in[0];
    float*      out = (float*)d_out;
    const int nsamp = in_sizes[0] / NAO2;

    Params P;
    cgbuild::build_params(P);

    cudaFuncSetAttribute(te_kernel, cudaFuncAttributeMaxDynamicSharedMemorySize, SMEM_BYTES);

    const int grid = (nsamp + SPB - 1) / SPB;
    te_kernel<<<grid, NTHR, SMEM_BYTES>>>(x, out, nsamp, P);
}